// round 1
// baseline (speedup 1.0000x reference)
#include <cuda_runtime.h>
#include <cuda_bf16.h>

#define NN 4096
#define FIN 128
#define FF 64
#define HH 8
#define MAXDEG 512

// scratch (allocation-free rule: device globals)
__device__ float g_feats[HH * NN * FF];   // [h][n][f]
__device__ float g_sself[HH * NN];
__device__ float g_sneigh[HH * NN];

// ---------------------------------------------------------------------------
// Kernel A: feats[h] = X @ W[h]   (fp32 tiled GEMM, 64x64 tile, K-chunks of 64)
// grid (N/64, H), block 256
// ---------------------------------------------------------------------------
__global__ __launch_bounds__(256) void gemm_feats_kernel(
    const float* __restrict__ X, const float* __restrict__ W)
{
    __shared__ float Xs[64 * 68];   // [row][k] padded
    __shared__ float Ws[64 * 68];   // [k][f]  padded

    const int h  = blockIdx.y;
    const int r0 = blockIdx.x * 64;
    const int tid = threadIdx.x;
    const int tx = tid & 15;        // f-tile  (16 x 4 cols)
    const int ty = tid >> 4;        // r-tile  (16 x 4 rows)

    float acc[4][4];
#pragma unroll
    for (int i = 0; i < 4; i++)
#pragma unroll
        for (int j = 0; j < 4; j++) acc[i][j] = 0.0f;

    for (int kc = 0; kc < FIN; kc += 64) {
        for (int i = tid; i < 64 * 64; i += 256) {
            int r = i >> 6, c = i & 63;
            Xs[r * 68 + c] = X[(r0 + r) * FIN + kc + c];
            Ws[r * 68 + c] = W[h * FIN * FF + (kc + r) * FF + c];
        }
        __syncthreads();
#pragma unroll 8
        for (int k = 0; k < 64; k++) {
            float a[4], b[4];
#pragma unroll
            for (int i = 0; i < 4; i++) a[i] = Xs[(ty * 4 + i) * 68 + k];
#pragma unroll
            for (int j = 0; j < 4; j++) b[j] = Ws[k * 68 + tx * 4 + j];
#pragma unroll
            for (int i = 0; i < 4; i++)
#pragma unroll
                for (int j = 0; j < 4; j++) acc[i][j] += a[i] * b[j];
        }
        __syncthreads();
    }

#pragma unroll
    for (int i = 0; i < 4; i++)
#pragma unroll
        for (int j = 0; j < 4; j++) {
            int n = r0 + ty * 4 + i;
            int f = tx * 4 + j;
            g_feats[h * NN * FF + n * FF + f] = acc[i][j];
        }
}

// ---------------------------------------------------------------------------
// Kernel B: s_self[h,n] = feats[h,n,:] . a_self[h,:]   (and s_neigh)
// one warp per (h,n). grid 4096, block 256 (8 warps)
// ---------------------------------------------------------------------------
__global__ __launch_bounds__(256) void score_kernel(
    const float* __restrict__ a_self, const float* __restrict__ a_neigh)
{
    const int warp = threadIdx.x >> 5;
    const int lane = threadIdx.x & 31;
    const int p = blockIdx.x * 8 + warp;       // p = h*NN + n
    const int h = p >> 12;

    float v0 = g_feats[p * FF + lane];
    float v1 = g_feats[p * FF + lane + 32];
    float ss = v0 * a_self[h * FF + lane]  + v1 * a_self[h * FF + lane + 32];
    float sn = v0 * a_neigh[h * FF + lane] + v1 * a_neigh[h * FF + lane + 32];
#pragma unroll
    for (int o = 16; o; o >>= 1) {
        ss += __shfl_xor_sync(0xffffffffu, ss, o);
        sn += __shfl_xor_sync(0xffffffffu, sn, o);
    }
    if (lane == 0) { g_sself[p] = ss; g_sneigh[p] = sn; }
}

// ---------------------------------------------------------------------------
// Kernel C: per-node sparse softmax + aggregation + ELU.
// Masked entries contribute exp(x - 1e10) == 0 exactly in fp32 (self-loop
// guarantees the row max is unmasked), so only true neighbors matter.
// grid 4096 (one block per node n), block 256
// ---------------------------------------------------------------------------
__global__ __launch_bounds__(256) void attn_kernel(
    const int* __restrict__ A, const float* __restrict__ bias,
    float* __restrict__ out)
{
    __shared__ int   s_idx[MAXDEG];
    __shared__ float s_w[HH * MAXDEG];
    __shared__ float s_ss[HH];
    __shared__ float s_inv[HH];
    __shared__ int   s_deg;

    const int n = blockIdx.x;
    const int tid = threadIdx.x;

    if (tid == 0) s_deg = 0;
    if (tid < HH) s_ss[tid] = g_sself[tid * NN + n];
    __syncthreads();

    // --- scan adjacency row, compact neighbor indices ---
    const int4* Arow = (const int4*)(A + (long long)n * NN);
    for (int i = tid; i < NN / 4; i += 256) {
        int4 v = Arow[i];
        int base = i * 4;
        if (v.x) { int p = atomicAdd(&s_deg, 1); if (p < MAXDEG) s_idx[p] = base; }
        if (v.y) { int p = atomicAdd(&s_deg, 1); if (p < MAXDEG) s_idx[p] = base + 1; }
        if (v.z) { int p = atomicAdd(&s_deg, 1); if (p < MAXDEG) s_idx[p] = base + 2; }
        if (v.w) { int p = atomicAdd(&s_deg, 1); if (p < MAXDEG) s_idx[p] = base + 3; }
    }
    __syncthreads();
    const int deg = min(s_deg, MAXDEG);

    // --- raw scores (LeakyReLU before mask, as in reference) ---
    for (int j = tid; j < deg; j += 256) {
        int m = s_idx[j];
#pragma unroll
        for (int h = 0; h < HH; h++) {
            float sc = s_ss[h] + g_sneigh[h * NN + m];
            sc = sc > 0.0f ? sc : 0.2f * sc;
            s_w[h * MAXDEG + j] = sc;
        }
    }
    __syncthreads();

    // --- per-head softmax: warp h handles head h ---
    {
        const int hh = tid >> 5;
        const int lane = tid & 31;
        float mx = -1e30f;
        for (int j = lane; j < deg; j += 32) mx = fmaxf(mx, s_w[hh * MAXDEG + j]);
#pragma unroll
        for (int o = 16; o; o >>= 1) mx = fmaxf(mx, __shfl_xor_sync(0xffffffffu, mx, o));
        float sum = 0.0f;
        for (int j = lane; j < deg; j += 32) {
            float e = __expf(s_w[hh * MAXDEG + j] - mx);
            s_w[hh * MAXDEG + j] = e;
            sum += e;
        }
#pragma unroll
        for (int o = 16; o; o >>= 1) sum += __shfl_xor_sync(0xffffffffu, sum, o);
        if (lane == 0) s_inv[hh] = 1.0f / sum;
    }
    __syncthreads();

    // --- weighted aggregation: thread t handles (h0=t>>6, f) and (h0+4, f) ---
    const int f  = tid & 63;
    const int h0 = tid >> 6;          // 0..3
    const int h1 = h0 + 4;
    const float* __restrict__ fb0 = g_feats + h0 * NN * FF + f;
    const float* __restrict__ fb1 = g_feats + h1 * NN * FF + f;
    const float* __restrict__ w0p = s_w + h0 * MAXDEG;
    const float* __restrict__ w1p = s_w + h1 * MAXDEG;

    float acc0 = 0.0f, acc1 = 0.0f;
    int j = 0;
    for (; j + 4 <= deg; j += 4) {
        int m0 = s_idx[j + 0], m1 = s_idx[j + 1], m2 = s_idx[j + 2], m3 = s_idx[j + 3];
        float v00 = fb0[m0 * FF], v01 = fb0[m1 * FF], v02 = fb0[m2 * FF], v03 = fb0[m3 * FF];
        float v10 = fb1[m0 * FF], v11 = fb1[m1 * FF], v12 = fb1[m2 * FF], v13 = fb1[m3 * FF];
        acc0 += w0p[j + 0] * v00; acc1 += w1p[j + 0] * v10;
        acc0 += w0p[j + 1] * v01; acc1 += w1p[j + 1] * v11;
        acc0 += w0p[j + 2] * v02; acc1 += w1p[j + 2] * v12;
        acc0 += w0p[j + 3] * v03; acc1 += w1p[j + 3] * v13;
    }
    for (; j < deg; j++) {
        int m = s_idx[j];
        acc0 += w0p[j] * fb0[m * FF];
        acc1 += w1p[j] * fb1[m * FF];
    }

    float o0 = acc0 * s_inv[h0] + bias[h0 * FF + f];
    float o1 = acc1 * s_inv[h1] + bias[h1 * FF + f];
    o0 = o0 > 0.0f ? o0 : expm1f(o0);
    o1 = o1 > 0.0f ? o1 : expm1f(o1);

    out[n * (HH * FF) + h0 * FF + f] = o0;
    out[n * (HH * FF) + h1 * FF + f] = o1;
}

// ---------------------------------------------------------------------------
extern "C" void kernel_launch(void* const* d_in, const int* in_sizes, int n_in,
                              void* d_out, int out_size)
{
    const float* X       = (const float*)d_in[0];   // [4096,128]
    const int*   A       = (const int*)  d_in[1];   // [4096,4096]
    const float* W       = (const float*)d_in[2];   // [8,128,64]
    const float* b       = (const float*)d_in[3];   // [8,64]
    const float* a_self  = (const float*)d_in[4];   // [8,64]
    const float* a_neigh = (const float*)d_in[5];   // [8,64]
    float* out = (float*)d_out;                     // [4096, 512]

    gemm_feats_kernel<<<dim3(NN / 64, HH), 256>>>(X, W);
    score_kernel<<<NN, 256>>>(a_self, a_neigh);
    attn_kernel<<<NN, 256>>>(A, b, out);
}

// round 5
// speedup vs baseline: 1.1188x; 1.1188x over previous
#include <cuda_runtime.h>
#include <cuda_fp16.h>
#include <cuda_bf16.h>

#define NN 4096
#define FIN 128
#define FF 64
#define HH 8
#define MAXDEG 512

// scratch (allocation-free rule: device globals)
__device__ float   g_feats[HH * NN * FF];        // fp32 [h][n][f] (for scores)
__device__ __half2 g_feats_h2[NN * HH * 32];     // fp16 [m][h][fpair] (for gather)
__device__ float   g_sself[HH * NN];
__device__ float   g_sneigh[HH * NN];

// ---------------------------------------------------------------------------
// Kernel A: feats[h] = X @ W[h].
// Tile 128 rows x 64 cols, block 256 threads, 8x4 per thread, K-chunks of 32.
// Epilogue writes fp32 [h][n][f] and fp16 [n][h][f].
// grid (NN/128, HH)
// ---------------------------------------------------------------------------
__global__ __launch_bounds__(256) void gemm_feats_kernel(
    const float* __restrict__ X, const float* __restrict__ W)
{
    __shared__ float Xs[32 * 132];   // transposed: [k][row], 128 rows + pad 4
    __shared__ float Ws[32 * 72];    // [k][f], 64 + pad 8

    const int h  = blockIdx.y;
    const int r0 = blockIdx.x * 128;
    const int tid = threadIdx.x;
    const int tx = tid & 15;         // f group: cols tx*4..tx*4+3
    const int ty = tid >> 4;         // row group: rows ty*8..ty*8+7

    float acc[8][4];
#pragma unroll
    for (int i = 0; i < 8; i++)
#pragma unroll
        for (int j = 0; j < 4; j++) acc[i][j] = 0.0f;

    for (int kc = 0; kc < FIN; kc += 32) {
        // load X chunk [128 rows][32 k] transposed into Xs[k][row]
        for (int i = tid; i < 128 * 8; i += 256) {       // 8 float4 per row
            int r = i >> 3, kq = (i & 7) * 4;
            float4 v = *(const float4*)(X + (r0 + r) * FIN + kc + kq);
            Xs[(kq + 0) * 132 + r] = v.x;
            Xs[(kq + 1) * 132 + r] = v.y;
            Xs[(kq + 2) * 132 + r] = v.z;
            Xs[(kq + 3) * 132 + r] = v.w;
        }
        // load W chunk [32 k][64 f]
        for (int i = tid; i < 32 * 16; i += 256) {       // 16 float4 per k-row
            int k = i >> 4, fq = (i & 15) * 4;
            float4 v = *(const float4*)(W + h * FIN * FF + (kc + k) * FF + fq);
            *(float4*)(Ws + k * 72 + fq) = v;
        }
        __syncthreads();

#pragma unroll
        for (int k = 0; k < 32; k++) {
            float4 a0 = *(const float4*)(Xs + k * 132 + ty * 8);
            float4 a1 = *(const float4*)(Xs + k * 132 + ty * 8 + 4);
            float4 b  = *(const float4*)(Ws + k * 72 + tx * 4);
            float a[8] = {a0.x, a0.y, a0.z, a0.w, a1.x, a1.y, a1.z, a1.w};
            float bb[4] = {b.x, b.y, b.z, b.w};
#pragma unroll
            for (int i = 0; i < 8; i++)
#pragma unroll
                for (int j = 0; j < 4; j++) acc[i][j] += a[i] * bb[j];
        }
        __syncthreads();
    }

#pragma unroll
    for (int i = 0; i < 8; i++) {
        int n = r0 + ty * 8 + i;
        int f = tx * 4;
        // fp32 for score kernel
        *(float4*)(g_feats + h * NN * FF + n * FF + f) =
            make_float4(acc[i][0], acc[i][1], acc[i][2], acc[i][3]);
        // fp16 [n][h][fpair] for the gather
        __half2 p0 = __floats2half2_rn(acc[i][0], acc[i][1]);
        __half2 p1 = __floats2half2_rn(acc[i][2], acc[i][3]);
        g_feats_h2[(n * HH + h) * 32 + (f >> 1)]     = p0;
        g_feats_h2[(n * HH + h) * 32 + (f >> 1) + 1] = p1;
    }
}

// ---------------------------------------------------------------------------
// Kernel B: s_self[h,n] = feats[h,n,:] . a_self[h,:]   (and s_neigh)
// one warp per (h,n). grid 4096 blocks x 8 warps = 32768 = H*N pairs
// ---------------------------------------------------------------------------
__global__ __launch_bounds__(256) void score_kernel(
    const float* __restrict__ a_self, const float* __restrict__ a_neigh)
{
    const int warp = threadIdx.x >> 5;
    const int lane = threadIdx.x & 31;
    const int p = blockIdx.x * 8 + warp;       // p = h*NN + n
    const int h = p >> 12;

    float v0 = g_feats[p * FF + lane];
    float v1 = g_feats[p * FF + lane + 32];
    float ss = v0 * a_self[h * FF + lane]  + v1 * a_self[h * FF + lane + 32];
    float sn = v0 * a_neigh[h * FF + lane] + v1 * a_neigh[h * FF + lane + 32];
#pragma unroll
    for (int o = 16; o; o >>= 1) {
        ss += __shfl_xor_sync(0xffffffffu, ss, o);
        sn += __shfl_xor_sync(0xffffffffu, sn, o);
    }
    if (lane == 0) { g_sself[p] = ss; g_sneigh[p] = sn; }
}

// ---------------------------------------------------------------------------
// Kernel C: per-node sparse softmax + aggregation + ELU.
// Masked entries contribute exp(x - 1e10) == 0 exactly in fp32 (self-loop
// guarantees the row max is unmasked), so only true neighbors matter.
// grid 4096 (one block per node n), block 256
// ---------------------------------------------------------------------------
__global__ __launch_bounds__(256) void attn_kernel(
    const int* __restrict__ A, const float* __restrict__ bias,
    float* __restrict__ out)
{
    __shared__ int   s_idx[MAXDEG];
    __shared__ float s_w[HH * MAXDEG];
    __shared__ float s_ss[HH];
    __shared__ float s_inv[HH];
    __shared__ int   s_deg;

    const int n = blockIdx.x;
    const int tid = threadIdx.x;

    if (tid == 0) s_deg = 0;
    if (tid < HH) s_ss[tid] = g_sself[tid * NN + n];
    __syncthreads();

    // --- scan adjacency row, compact neighbor indices ---
    const int4* Arow = (const int4*)(A + (long long)n * NN);
    for (int i = tid; i < NN / 4; i += 256) {
        int4 v = Arow[i];
        int base = i * 4;
        if (v.x) { int p = atomicAdd(&s_deg, 1); if (p < MAXDEG) s_idx[p] = base; }
        if (v.y) { int p = atomicAdd(&s_deg, 1); if (p < MAXDEG) s_idx[p] = base + 1; }
        if (v.z) { int p = atomicAdd(&s_deg, 1); if (p < MAXDEG) s_idx[p] = base + 2; }
        if (v.w) { int p = atomicAdd(&s_deg, 1); if (p < MAXDEG) s_idx[p] = base + 3; }
    }
    __syncthreads();
    const int deg = min(s_deg, MAXDEG);

    // --- raw scores (LeakyReLU before mask, as in reference) ---
    for (int j = tid; j < deg; j += 256) {
        int m = s_idx[j];
#pragma unroll
        for (int h = 0; h < HH; h++) {
            float sc = s_ss[h] + g_sneigh[h * NN + m];
            sc = sc > 0.0f ? sc : 0.2f * sc;
            s_w[h * MAXDEG + j] = sc;
        }
    }
    __syncthreads();

    // --- per-head softmax: warp h handles head h ---
    {
        const int hh = tid >> 5;
        const int lane = tid & 31;
        float mx = -1e30f;
        for (int j = lane; j < deg; j += 32) mx = fmaxf(mx, s_w[hh * MAXDEG + j]);
#pragma unroll
        for (int o = 16; o; o >>= 1) mx = fmaxf(mx, __shfl_xor_sync(0xffffffffu, mx, o));
        float sum = 0.0f;
        for (int j = lane; j < deg; j += 32) {
            float e = __expf(s_w[hh * MAXDEG + j] - mx);
            s_w[hh * MAXDEG + j] = e;
            sum += e;
        }
#pragma unroll
        for (int o = 16; o; o >>= 1) sum += __shfl_xor_sync(0xffffffffu, sum, o);
        if (lane == 0) s_inv[hh] = 1.0f / sum;
    }
    __syncthreads();

    // --- weighted aggregation from fp16 feats [m][h][fpair] ---
    // thread t: head h = t>>5, fpair fp = t&31 -> output cols h*64 + 2*fp, 2*fp+1
    const int h  = tid >> 5;
    const int fp = tid & 31;
    const __half2* __restrict__ fb = g_feats_h2 + h * 32 + fp;   // + m*256
    const float*   __restrict__ wp = s_w + h * MAXDEG;

    float accx = 0.0f, accy = 0.0f;
    int j = 0;
    for (; j + 4 <= deg; j += 4) {
        int m0 = s_idx[j + 0], m1 = s_idx[j + 1], m2 = s_idx[j + 2], m3 = s_idx[j + 3];
        __half2 v0 = fb[m0 * (HH * 32)];
        __half2 v1 = fb[m1 * (HH * 32)];
        __half2 v2 = fb[m2 * (HH * 32)];
        __half2 v3 = fb[m3 * (HH * 32)];
        float w0 = wp[j + 0], w1 = wp[j + 1], w2 = wp[j + 2], w3 = wp[j + 3];
        float2 f0 = __half22float2(v0), f1 = __half22float2(v1);
        float2 f2 = __half22float2(v2), f3 = __half22float2(v3);
        accx += w0 * f0.x + w1 * f1.x + w2 * f2.x + w3 * f3.x;
        accy += w0 * f0.y + w1 * f1.y + w2 * f2.y + w3 * f3.y;
    }
    for (; j < deg; j++) {
        int m = s_idx[j];
        float2 f = __half22float2(fb[m * (HH * 32)]);
        float w = wp[j];
        accx += w * f.x;
        accy += w * f.y;
    }

    const float inv = s_inv[h];
    float o0 = accx * inv + bias[h * FF + fp * 2];
    float o1 = accy * inv + bias[h * FF + fp * 2 + 1];
    o0 = o0 > 0.0f ? o0 : expm1f(o0);
    o1 = o1 > 0.0f ? o1 : expm1f(o1);

    *(float2*)(out + n * (HH * FF) + h * FF + fp * 2) = make_float2(o0, o1);
}

// ---------------------------------------------------------------------------
extern "C" void kernel_launch(void* const* d_in, const int* in_sizes, int n_in,
                              void* d_out, int out_size)
{
    const float* X       = (const float*)d_in[0];   // [4096,128]
    const int*   A       = (const int*)  d_in[1];   // [4096,4096]
    const float* W       = (const float*)d_in[2];   // [8,128,64]
    const float* b       = (const float*)d_in[3];   // [8,64]
    const float* a_self  = (const float*)d_in[4];   // [8,64]
    const float* a_neigh = (const float*)d_in[5];   // [8,64]
    float* out = (float*)d_out;                     // [4096, 512]

    gemm_feats_kernel<<<dim3(NN / 128, HH), 256>>>(X, W);
    score_kernel<<<NN, 256>>>(a_self, a_neigh);
    attn_kernel<<<NN, 256>>>(A, b, out);
}